// round 14
// baseline (speedup 1.0000x reference)
#include <cuda_runtime.h>
#include <cuda_fp16.h>
#include <cstdint>

// Problem constants (fixed)
#define K_DIM 4096
#define N_DIM 4096
#define M_DIM 4096
#define GROUPS 32

// fp16 scratch: dequantized weights [N,K] and converted activations [M,K]
__device__ __half g_w[(size_t)N_DIM * K_DIM];
__device__ __half g_x[(size_t)M_DIM * K_DIM];

// ---------------------------------------------------------------------------
// Fused prep: blocks [0, 8192) dequant int4->fp16 W; blocks [8192, 16384) x->fp16
// ---------------------------------------------------------------------------
#define DQ_BLOCKS 8192

__global__ __launch_bounds__(256) void prep_kernel(
    const int* __restrict__ qw, const int* __restrict__ qz,
    const float* __restrict__ sc, const float* __restrict__ x)
{
    if (blockIdx.x < DQ_BLOCKS) {
        int idx = blockIdx.x * blockDim.x + threadIdx.x;   // 0 .. N*K/8
        int n = idx >> 9;
        int k8 = idx & 511;
        int g = k8 >> 4;

        unsigned v = (unsigned)qw[idx];
        unsigned zv = (unsigned)qz[(n << 2) + (g >> 3)];
        float z = (float)((zv >> ((g & 7) * 4)) & 15u);
        float s = sc[(n << 5) + g];

        __half2 h[4];
#pragma unroll
        for (int j = 0; j < 4; j++) {
            float lo = ((float)((v >> (8 * j)) & 15u) - z) * s;
            float hi = ((float)((v >> (8 * j + 4)) & 15u) - z) * s;
            h[j] = __floats2half2_rn(lo, hi);
        }
        *(uint4*)(g_w + (size_t)n * K_DIM + (size_t)k8 * 8) = *(uint4*)h;
    } else {
        int i = (blockIdx.x - DQ_BLOCKS) * blockDim.x + threadIdx.x;  // 0 .. M*K/8
        float4 a = ((const float4*)x)[i * 2];
        float4 b = ((const float4*)x)[i * 2 + 1];
        __half2 h[4];
        h[0] = __floats2half2_rn(a.x, a.y);
        h[1] = __floats2half2_rn(a.z, a.w);
        h[2] = __floats2half2_rn(b.x, b.y);
        h[3] = __floats2half2_rn(b.z, b.w);
        ((uint4*)g_x)[i] = *(uint4*)h;
    }
}

// ---------------------------------------------------------------------------
// fp16 mma.sync GEMM: C[m][n] = sum_k x[m][k]*w[n][k] + bias[n]
// ONE 512-thread CTA per SM. CTA tile 128x256, BK=64, 3-stage cp.async.
// 16 warps (2M x 8N), warp tile 64x32. Stage = A 16KB + B 32KB = 48KB; x3 = 144KB.
// smem rows: 128B, swizzle chunk ^= (row & 7) -> conflict-free.
// ---------------------------------------------------------------------------
#define BM 128
#define BN 256
#define BK 64
#define STAGES 3
#define K_ITERS (K_DIM / BK)               // 64
#define A_BYTES (BM * BK * 2)               // 16384
#define B_BYTES (BN * BK * 2)               // 32768
#define STAGE_BYTES (A_BYTES + B_BYTES)     // 49152
#define SMEM_TOTAL (STAGES * STAGE_BYTES)   // 147456
#define NTHREADS 512

__device__ __forceinline__ uint32_t smem_u32(const void* p) {
    uint32_t a;
    asm("{ .reg .u64 t; cvta.to.shared.u64 t, %1; cvt.u32.u64 %0, t; }" : "=r"(a) : "l"(p));
    return a;
}

__device__ __forceinline__ void ldm_x4(uint32_t* r, uint32_t addr) {
    asm volatile("ldmatrix.sync.aligned.m8n8.x4.shared.b16 {%0,%1,%2,%3}, [%4];"
                 : "=r"(r[0]), "=r"(r[1]), "=r"(r[2]), "=r"(r[3]) : "r"(addr));
}

__device__ __forceinline__ void mma16816(float* d, const uint32_t* a,
                                         uint32_t b0, uint32_t b1) {
    asm volatile(
        "mma.sync.aligned.m16n8k16.row.col.f32.f16.f16.f32 "
        "{%0,%1,%2,%3}, {%4,%5,%6,%7}, {%8,%9}, {%0,%1,%2,%3};"
        : "+f"(d[0]), "+f"(d[1]), "+f"(d[2]), "+f"(d[3])
        : "r"(a[0]), "r"(a[1]), "r"(a[2]), "r"(a[3]), "r"(b0), "r"(b1));
}

__device__ __forceinline__ void load_stage(uint32_t sb, int slot, int kt,
                                           int bm, int bn, int tid)
{
    uint32_t st = sb + slot * STAGE_BYTES;
    // A: 128 rows x 8 chunks(16B) = 1024; 2 per thread (512 threads)
#pragma unroll
    for (int t = 0; t < 2; t++) {
        int ci = tid + t * NTHREADS;
        int row = ci >> 3;
        int c = ci & 7;
        uint32_t sw = (uint32_t)(row * 128 + ((c ^ (row & 7)) << 4));
        const __half* ga = g_x + (size_t)(bm + row) * K_DIM + kt + c * 8;
        asm volatile("cp.async.cg.shared.global [%0], [%1], 16;"
                     :: "r"(st + sw), "l"(ga) : "memory");
    }
    // B: 256 rows x 8 chunks = 2048; 4 per thread
#pragma unroll
    for (int t = 0; t < 4; t++) {
        int ci = tid + t * NTHREADS;
        int row = ci >> 3;
        int c = ci & 7;
        uint32_t sw = (uint32_t)(row * 128 + ((c ^ (row & 7)) << 4));
        const __half* gb = g_w + (size_t)(bn + row) * K_DIM + kt + c * 8;
        asm volatile("cp.async.cg.shared.global [%0], [%1], 16;"
                     :: "r"(st + A_BYTES + sw), "l"(gb) : "memory");
    }
}

__global__ __launch_bounds__(NTHREADS, 1) void gemm_hmma_kernel(
    const float* __restrict__ bias, float* __restrict__ C)
{
    extern __shared__ char smem[];
    uint32_t sb = smem_u32(smem);
    int tid = threadIdx.x;
    int lane = tid & 31;
    int wid = tid >> 5;
    int warp_m = wid & 1;       // 2 M-slots of 64
    int warp_n = wid >> 1;      // 8 N-slots of 32
    int bm = blockIdx.y * BM;
    int bn = blockIdx.x * BN;

    // ldmatrix lane decomposition
    int ar = (lane & 7) + ((lane >> 3) & 1) * 8;   // A row within 16
    int acb = lane >> 4;                            // A k16 half-chunk (0/1)
    int br = (lane & 7) + ((lane >> 4) & 1) * 8;   // B n-row within 16
    int bcb = (lane >> 3) & 1;                      // B k16 half-chunk

    float acc[4][4][4];
#pragma unroll
    for (int i = 0; i < 4; i++)
#pragma unroll
        for (int j = 0; j < 4; j++)
#pragma unroll
            for (int t = 0; t < 4; t++) acc[i][j][t] = 0.0f;

    // prologue: fill STAGES-1 stages
#pragma unroll
    for (int p = 0; p < STAGES - 1; p++) {
        load_stage(sb, p, p * BK, bm, bn, tid);
        asm volatile("cp.async.commit_group;" ::: "memory");
    }

    // main loop unrolled by STAGES so slots are compile-time
    for (int itb = 0; itb < K_ITERS; itb += STAGES) {
#pragma unroll
        for (int s = 0; s < STAGES; s++) {
            int it = itb + s;
            // K_ITERS=64, STAGES=3: last block partial (64 = 21*3 + 1)
            if (it >= K_ITERS) break;

            asm volatile("cp.async.wait_group %0;" :: "n"(STAGES - 2) : "memory");
            __syncthreads();

            int nxt = it + STAGES - 1;
            if (nxt < K_ITERS) {
                int ns = s + STAGES - 1;
                if (ns >= STAGES) ns -= STAGES;
                load_stage(sb, ns, nxt * BK, bm, bn, tid);
            }
            asm volatile("cp.async.commit_group;" ::: "memory");

            uint32_t Ab = sb + s * STAGE_BYTES;
            uint32_t Bb = Ab + A_BYTES;

#pragma unroll
            for (int ks = 0; ks < 4; ks++) {           // 4 k16 steps per BK=64
                uint32_t a[4][4];
#pragma unroll
                for (int mt = 0; mt < 4; mt++) {
                    int row = warp_m * 64 + mt * 16 + ar;
                    uint32_t addr = Ab + row * 128 +
                        (((ks * 2 + acb) ^ (row & 7)) << 4);
                    ldm_x4(a[mt], addr);
                }
                uint32_t b[2][4];
#pragma unroll
                for (int np = 0; np < 2; np++) {       // 2 n16 groups = 32 N
                    int row = warp_n * 32 + np * 16 + br;
                    uint32_t addr = Bb + row * 128 +
                        (((ks * 2 + bcb) ^ (row & 7)) << 4);
                    ldm_x4(b[np], addr);
                }
#pragma unroll
                for (int mt = 0; mt < 4; mt++)
#pragma unroll
                    for (int nt = 0; nt < 4; nt++)
                        mma16816(acc[mt][nt], a[mt],
                                 b[nt >> 1][(nt & 1) * 2], b[nt >> 1][(nt & 1) * 2 + 1]);
            }
        }
    }

    // epilogue: direct fp32 stores + bias
    int gr = lane >> 2;
    int gc = (lane & 3) * 2;
#pragma unroll
    for (int nt = 0; nt < 4; nt++) {
        int col = bn + warp_n * 32 + nt * 8 + gc;
        float b0 = __ldg(bias + col);
        float b1 = __ldg(bias + col + 1);
#pragma unroll
        for (int mt = 0; mt < 4; mt++) {
            int row = bm + warp_m * 64 + mt * 16 + gr;
            float2 v0 = make_float2(acc[mt][nt][0] + b0, acc[mt][nt][1] + b1);
            float2 v1 = make_float2(acc[mt][nt][2] + b0, acc[mt][nt][3] + b1);
            *(float2*)(C + (size_t)row * N_DIM + col) = v0;
            *(float2*)(C + (size_t)(row + 8) * N_DIM + col) = v1;
        }
    }
}

// ---------------------------------------------------------------------------
extern "C" void kernel_launch(void* const* d_in, const int* in_sizes, int n_in,
                              void* d_out, int out_size)
{
    const float* x    = (const float*)d_in[0];
    const int*   qw   = (const int*)d_in[1];
    const int*   qz   = (const int*)d_in[2];
    const float* sc   = (const float*)d_in[3];
    const float* bias = (const float*)d_in[4];
    float* out = (float*)d_out;

    int tokens = in_sizes[0] / K_DIM;   // 4096

    int cx_blocks = tokens * K_DIM / 8 / 256;
    prep_kernel<<<DQ_BLOCKS + cx_blocks, 256>>>(qw, qz, sc, x);

    cudaFuncSetAttribute(gemm_hmma_kernel,
                         cudaFuncAttributeMaxDynamicSharedMemorySize, SMEM_TOTAL);
    dim3 grid(N_DIM / BN, tokens / BM);
    gemm_hmma_kernel<<<grid, NTHREADS, SMEM_TOTAL>>>(bias, out);
}

// round 15
// speedup vs baseline: 1.2306x; 1.2306x over previous
#include <cuda_runtime.h>
#include <cuda_fp16.h>
#include <cstdint>

// Problem constants (fixed)
#define K_DIM 4096
#define N_DIM 4096
#define M_DIM 4096
#define GROUPS 32

// fp16 scratch: dequantized weights [N,K] and converted activations [M,K]
__device__ __half g_w[(size_t)N_DIM * K_DIM];
__device__ __half g_x[(size_t)M_DIM * K_DIM];

// ---------------------------------------------------------------------------
// Fused prep: blocks [0, 8192) dequant int4->fp16 W; blocks [8192, 16384) x->fp16
// ---------------------------------------------------------------------------
#define DQ_BLOCKS 8192

__global__ __launch_bounds__(256) void prep_kernel(
    const int* __restrict__ qw, const int* __restrict__ qz,
    const float* __restrict__ sc, const float* __restrict__ x)
{
    if (blockIdx.x < DQ_BLOCKS) {
        int idx = blockIdx.x * blockDim.x + threadIdx.x;   // 0 .. N*K/8
        int n = idx >> 9;
        int k8 = idx & 511;
        int g = k8 >> 4;

        unsigned v = (unsigned)qw[idx];
        unsigned zv = (unsigned)qz[(n << 2) + (g >> 3)];
        float z = (float)((zv >> ((g & 7) * 4)) & 15u);
        float s = sc[(n << 5) + g];

        __half2 h[4];
#pragma unroll
        for (int j = 0; j < 4; j++) {
            float lo = ((float)((v >> (8 * j)) & 15u) - z) * s;
            float hi = ((float)((v >> (8 * j + 4)) & 15u) - z) * s;
            h[j] = __floats2half2_rn(lo, hi);
        }
        *(uint4*)(g_w + (size_t)n * K_DIM + (size_t)k8 * 8) = *(uint4*)h;
    } else {
        int i = (blockIdx.x - DQ_BLOCKS) * blockDim.x + threadIdx.x;  // 0 .. M*K/8
        float4 a = ((const float4*)x)[i * 2];
        float4 b = ((const float4*)x)[i * 2 + 1];
        __half2 h[4];
        h[0] = __floats2half2_rn(a.x, a.y);
        h[1] = __floats2half2_rn(a.z, a.w);
        h[2] = __floats2half2_rn(b.x, b.y);
        h[3] = __floats2half2_rn(b.z, b.w);
        ((uint4*)g_x)[i] = *(uint4*)h;
    }
}

// ---------------------------------------------------------------------------
// fp16 mma.sync GEMM: C[m][n] = sum_k x[m][k]*w[n][k] + bias[n]
// BM=BN=128, BK=64, 3-stage cp.async, 8 warps (2M x 4N), warp tile 64x32
// Outer loop unrolled x3 -> compile-time stage slots (immediate smem offsets).
// smem rows: 128B, swizzle chunk ^= (row & 7); 96KB/CTA -> 2 CTAs/SM
// ---------------------------------------------------------------------------
#define BM 128
#define BN 128
#define BK 64
#define STAGES 3
#define K_ITERS (K_DIM / BK)            // 64
#define A_BYTES (BM * BK * 2)            // 16384
#define STAGE_BYTES (2 * A_BYTES)        // 32768
#define SMEM_TOTAL (STAGES * STAGE_BYTES)  // 98304

__device__ __forceinline__ uint32_t smem_u32(const void* p) {
    uint32_t a;
    asm("{ .reg .u64 t; cvta.to.shared.u64 t, %1; cvt.u32.u64 %0, t; }" : "=r"(a) : "l"(p));
    return a;
}

__device__ __forceinline__ void ldm_x4(uint32_t* r, uint32_t addr) {
    asm volatile("ldmatrix.sync.aligned.m8n8.x4.shared.b16 {%0,%1,%2,%3}, [%4];"
                 : "=r"(r[0]), "=r"(r[1]), "=r"(r[2]), "=r"(r[3]) : "r"(addr));
}

__device__ __forceinline__ void mma16816(float* d, const uint32_t* a,
                                         uint32_t b0, uint32_t b1) {
    asm volatile(
        "mma.sync.aligned.m16n8k16.row.col.f32.f16.f16.f32 "
        "{%0,%1,%2,%3}, {%4,%5,%6,%7}, {%8,%9}, {%0,%1,%2,%3};"
        : "+f"(d[0]), "+f"(d[1]), "+f"(d[2]), "+f"(d[3])
        : "r"(a[0]), "r"(a[1]), "r"(a[2]), "r"(a[3]), "r"(b0), "r"(b1));
}

__device__ __forceinline__ void load_stage(uint32_t sb, int slot, int kt,
                                           int bm, int bn, int tid)
{
    uint32_t st = sb + slot * STAGE_BYTES;
#pragma unroll
    for (int t = 0; t < 4; t++) {
        int ci = tid + t * 256;
        int row = ci >> 3;
        int c = ci & 7;
        uint32_t sw = (uint32_t)(row * 128 + ((c ^ (row & 7)) << 4));
        const __half* ga = g_x + (size_t)(bm + row) * K_DIM + kt + c * 8;
        asm volatile("cp.async.cg.shared.global [%0], [%1], 16;"
                     :: "r"(st + sw), "l"(ga) : "memory");
        const __half* gb = g_w + (size_t)(bn + row) * K_DIM + kt + c * 8;
        asm volatile("cp.async.cg.shared.global [%0], [%1], 16;"
                     :: "r"(st + A_BYTES + sw), "l"(gb) : "memory");
    }
}

struct Frag { uint32_t a[4][4]; uint32_t b[2][4]; };

__global__ __launch_bounds__(256, 2) void gemm_hmma_kernel(
    const float* __restrict__ bias, float* __restrict__ C)
{
    extern __shared__ char smem[];
    uint32_t sb = smem_u32(smem);
    int tid = threadIdx.x;
    int lane = tid & 31;
    int wid = tid >> 5;
    int warp_m = wid & 1;       // 2 M-slots of 64
    int warp_n = wid >> 1;      // 4 N-slots of 32
    int bm = blockIdx.y * BM;
    int bn = blockIdx.x * BN;

    // ldmatrix lane decomposition
    int ar = (lane & 7) + ((lane >> 3) & 1) * 8;   // A row within 16
    int acb = lane >> 4;                            // A k16 half-chunk (0/1)
    int br = (lane & 7) + ((lane >> 4) & 1) * 8;   // B n-row within 16
    int bcb = (lane >> 3) & 1;                      // B k16 half-chunk

    float acc[4][4][4];
#pragma unroll
    for (int i = 0; i < 4; i++)
#pragma unroll
        for (int j = 0; j < 4; j++)
#pragma unroll
            for (int t = 0; t < 4; t++) acc[i][j][t] = 0.0f;

    // prologue: fill STAGES-1 stages
#pragma unroll
    for (int p = 0; p < STAGES - 1; p++) {
        load_stage(sb, p, p * BK, bm, bn, tid);
        asm volatile("cp.async.commit_group;" ::: "memory");
    }

    // main loop: K_ITERS=64 = 21*3 + 1; unroll by 3 for compile-time slots
    for (int itb = 0; itb < K_ITERS; itb += STAGES) {
#pragma unroll
        for (int s = 0; s < STAGES; s++) {
            int it = itb + s;
            if (it >= K_ITERS) break;

            asm volatile("cp.async.wait_group %0;" :: "n"(STAGES - 2) : "memory");
            __syncthreads();

            int nxt = it + STAGES - 1;
            if (nxt < K_ITERS) {
                int ns = (s + STAGES - 1 >= STAGES) ? s - 1 : s + STAGES - 1;
                load_stage(sb, ns, nxt * BK, bm, bn, tid);
            }
            asm volatile("cp.async.commit_group;" ::: "memory");

            uint32_t Ab = sb + s * STAGE_BYTES;     // s compile-time
            uint32_t Bb = Ab + A_BYTES;

#pragma unroll
            for (int ks = 0; ks < 4; ks++) {        // 4 k16 steps per BK=64
                // B first (2 loads), then A (4): max distance from a[0] to use
                uint32_t b[2][4];
#pragma unroll
                for (int np = 0; np < 2; np++) {
                    int row = warp_n * 32 + np * 16 + br;
                    uint32_t addr = Bb + row * 128 +
                        (((ks * 2 + bcb) ^ (row & 7)) << 4);
                    ldm_x4(b[np], addr);
                }
                uint32_t a[4][4];
#pragma unroll
                for (int mt = 0; mt < 4; mt++) {
                    int row = warp_m * 64 + mt * 16 + ar;
                    uint32_t addr = Ab + row * 128 +
                        (((ks * 2 + acb) ^ (row & 7)) << 4);
                    ldm_x4(a[mt], addr);
                }
#pragma unroll
                for (int mt = 0; mt < 4; mt++)
#pragma unroll
                    for (int nt = 0; nt < 4; nt++)
                        mma16816(acc[mt][nt], a[mt],
                                 b[nt >> 1][(nt & 1) * 2], b[nt >> 1][(nt & 1) * 2 + 1]);
            }
        }
    }

    // epilogue: direct fp32 stores + bias
    int gr = lane >> 2;
    int gc = (lane & 3) * 2;
#pragma unroll
    for (int nt = 0; nt < 4; nt++) {
        int col = bn + warp_n * 32 + nt * 8 + gc;
        float b0 = __ldg(bias + col);
        float b1 = __ldg(bias + col + 1);
#pragma unroll
        for (int mt = 0; mt < 4; mt++) {
            int row = bm + warp_m * 64 + mt * 16 + gr;
            float2 v0 = make_float2(acc[mt][nt][0] + b0, acc[mt][nt][1] + b1);
            float2 v1 = make_float2(acc[mt][nt][2] + b0, acc[mt][nt][3] + b1);
            *(float2*)(C + (size_t)row * N_DIM + col) = v0;
            *(float2*)(C + (size_t)(row + 8) * N_DIM + col) = v1;
        }
    }
}

// ---------------------------------------------------------------------------
extern "C" void kernel_launch(void* const* d_in, const int* in_sizes, int n_in,
                              void* d_out, int out_size)
{
    const float* x    = (const float*)d_in[0];
    const int*   qw   = (const int*)d_in[1];
    const int*   qz   = (const int*)d_in[2];
    const float* sc   = (const float*)d_in[3];
    const float* bias = (const float*)d_in[4];
    float* out = (float*)d_out;

    int tokens = in_sizes[0] / K_DIM;   // 4096

    int cx_blocks = tokens * K_DIM / 8 / 256;
    prep_kernel<<<DQ_BLOCKS + cx_blocks, 256>>>(qw, qz, sc, x);

    cudaFuncSetAttribute(gemm_hmma_kernel,
                         cudaFuncAttributeMaxDynamicSharedMemorySize, SMEM_TOTAL);
    dim3 grid(N_DIM / BN, tokens / BM);
    gemm_hmma_kernel<<<grid, 256, SMEM_TOTAL>>>(bias, out);
}